// round 2
// baseline (speedup 1.0000x reference)
#include <cuda_runtime.h>
#include <math.h>

#define BB   8
#define NN   512
#define DD   128
#define HH   64
#define FNN  3
#define BN   4096
#define MAXDEG 192

// ---------------- device scratch ----------------
__device__ float g_wm1;
__device__ float g_kap[BN];
__device__ float g_f[FNN][BN];
__device__ int   g_rank[BN];
__device__ int   g_cnt[BN];
__device__ int   g_adj[BN][MAXDEG];
__device__ float g_af[FNN][BN];
__device__ float g_gam[FNN][BN], g_df[FNN][BN], g_fdf[FNN][BN];
__device__ float g_term[BN];
__device__ float g_h[3][BN * HH];

// ---------------- wm1 = weight_mlp(1.0) scalar ----------------
__global__ void k_wm1(const float* __restrict__ W1, const float* __restrict__ b1,
                      const float* __restrict__ W2, const float* __restrict__ b2,
                      const float* __restrict__ W3, const float* __restrict__ b3) {
    __shared__ float h1[64], h2[32];
    int t = threadIdx.x;
    h1[t] = fmaxf(W1[t] + b1[t], 0.f);
    __syncthreads();
    if (t < 32) {
        float s = b2[t];
        for (int k = 0; k < 64; k++) s = fmaf(h1[k], W2[k * 32 + t], s);
        h2[t] = fmaxf(s, 0.f);
    }
    __syncthreads();
    if (t == 0) {
        float s = b3[0];
        for (int k = 0; k < 32; k++) s = fmaf(h2[k], W3[k], s);
        g_wm1 = 1.f / (1.f + expf(-s));
    }
}

// ---------------- CSR build: float4 loads + warp-scan compaction ----------------
// grid 2048, block 256 (2 rows/block, 128 threads/row)
__global__ void k_adj(const float* __restrict__ A) {
    int r2 = threadIdx.x >> 7;              // which row half
    int row = blockIdx.x * 2 + r2;
    int t = threadIdx.x & 127;              // thread within row
    int lane = threadIdx.x & 31;
    int w = (threadIdx.x >> 5) & 3;         // warp within row
    float4 v = ((const float4*)(A + (size_t)row * 512))[t];
    unsigned flags = (v.x != 0.f ? 1u : 0u) | (v.y != 0.f ? 2u : 0u) |
                     (v.z != 0.f ? 4u : 0u) | (v.w != 0.f ? 8u : 0u);
    int c = __popc(flags);
    int sc = c;
    #pragma unroll
    for (int o = 1; o < 32; o <<= 1) {
        int n = __shfl_up_sync(0xffffffffu, sc, o);
        if (lane >= o) sc += n;
    }
    __shared__ int wsum[2][4];
    if (lane == 31) wsum[r2][w] = sc;
    __syncthreads();
    int wbase = 0;
    #pragma unroll
    for (int i = 0; i < 4; i++) if (i < w) wbase += wsum[r2][i];
    int off = wbase + sc - c;               // exclusive prefix
    int col = t * 4;
    #pragma unroll
    for (int k = 0; k < 4; k++) {
        if ((flags >> k) & 1u) {
            if (off < MAXDEG) g_adj[row][off] = col + k;
            off++;
        }
    }
    if (t == 127) g_cnt[row] = wbase + sc;
}

// ---------------- per-node MLPs (kappa + f0..f2), tiled 16 rows/block ----------------
// grid (256, 4), block 256
__global__ void k_node(const float* __restrict__ X,
                       const float* __restrict__ cW1, const float* __restrict__ cb1,
                       const float* __restrict__ cW2, const float* __restrict__ cb2,
                       const float* __restrict__ fW1, const float* __restrict__ fb1,
                       const float* __restrict__ fW2, const float* __restrict__ fb2) {
    __shared__ float sW[128 * 64];   // 32KB
    __shared__ float sX[16 * 128];   // 8KB
    __shared__ float sP[16 * 68];    // padded
    int m = blockIdx.y;
    const float* W1 = (m == 0) ? cW1 : fW1 + (m - 1) * 8192;
    const float* b1 = (m == 0) ? cb1 : fb1 + (m - 1) * 64;
    const float* W2 = (m == 0) ? cW2 : fW2 + (m - 1) * 64;
    int row0 = blockIdx.x * 16;
    int t = threadIdx.x;
    for (int i = t; i < 2048; i += 256) ((float4*)sW)[i] = ((const float4*)W1)[i];
    for (int i = t; i < 512;  i += 256) ((float4*)sX)[i] = ((const float4*)(X + (size_t)row0 * 128))[i];
    __syncthreads();
    int hid = t & 63, rsub = t >> 6;
    float b1v = b1[hid], w2v = W2[hid];
    #pragma unroll
    for (int pass = 0; pass < 4; pass++) {
        int r = pass * 4 + rsub;
        float a = b1v;
        const float* xr = sX + r * 128;
        #pragma unroll 16
        for (int d = 0; d < 128; d++) a = fmaf(xr[d], sW[d * 64 + hid], a);
        sP[r * 68 + hid] = fmaxf(a, 0.f) * w2v;
    }
    __syncthreads();
    if (t < 16) {
        float bb2 = (m == 0) ? cb2[0] : fb2[m - 1];
        float s = bb2;
        const float* pr = sP + t * 68;
        #pragma unroll
        for (int k = 0; k < 64; k++) s += pr[k];
        float v = 1.f / (1.f + expf(-s));
        int row = row0 + t;
        if (m == 0) g_kap[row] = v; else g_f[m - 1][row] = v;
    }
}

// ---------------- per-batch rank of kappa (desc value, asc index) ----------------
__device__ __forceinline__ bool before_cmp(float va, int ia, float vb, int ib) {
    return (va > vb) || (va == vb && ia < ib);
}
__global__ void k_rank() {
    __shared__ float sv[512];
    __shared__ int   si[512];
    int b = blockIdx.x, t = threadIdx.x;
    sv[t] = g_kap[b * 512 + t];
    si[t] = t;
    __syncthreads();
    for (int k = 2; k <= 512; k <<= 1) {
        for (int j = k >> 1; j > 0; j >>= 1) {
            int ixj = t ^ j;
            if (ixj > t) {
                float va = sv[t], vb = sv[ixj];
                int ia = si[t], ib = si[ixj];
                bool up = ((t & k) == 0);
                bool sw = up ? before_cmp(vb, ib, va, ia) : before_cmp(va, ia, vb, ib);
                if (sw) { sv[t] = vb; si[t] = ib; sv[ixj] = va; si[ixj] = ia; }
            }
            __syncthreads();
        }
    }
    g_rank[b * 512 + si[t]] = t;
}

// ---------------- spmv1 (A@f, A@f^2) + fused elementwise (gamma, df, f*df) ----------------
// grid 1024, block 128 (4 rows/block, 1 warp/row)
__global__ void k_spmv1() {
    int row = blockIdx.x * 4 + (threadIdx.x >> 5);
    int lane = threadIdx.x & 31;
    int base = row & ~511;
    int cnt = min(g_cnt[row], MAXDEG);
    float af[FNN] = {0, 0, 0}, aq[FNN] = {0, 0, 0};
    for (int n = lane; n < cnt; n += 32) {
        int gc = base + g_adj[row][n];
        #pragma unroll
        for (int i = 0; i < FNN; i++) {
            float fv = g_f[i][gc];
            af[i] += fv; aq[i] += fv * fv;
        }
    }
    #pragma unroll
    for (int i = 0; i < FNN; i++) {
        #pragma unroll
        for (int o = 16; o > 0; o >>= 1) {
            af[i] += __shfl_down_sync(0xffffffffu, af[i], o);
            aq[i] += __shfl_down_sync(0xffffffffu, aq[i], o);
        }
    }
    if (lane == 0) {
        float w1 = g_wm1;
        float degw = w1 * (float)cnt;
        #pragma unroll
        for (int i = 0; i < FNN; i++) {
            float f = g_f[i][row];
            float wf = w1 * af[i];
            float gamma = 0.5f * (f * f * degw - 2.f * f * wf + w1 * aq[i]);
            float df = f * degw - wf;
            g_af[i][row] = af[i];
            g_gam[i][row] = gamma; g_df[i][row] = df; g_fdf[i][row] = f * df;
        }
    }
}

// ---------------- spmv2 (A@gamma, A@df, A@fdf) + fused per-row loss term ----------------
__global__ void k_spmv2() {
    int row = blockIdx.x * 4 + (threadIdx.x >> 5);
    int lane = threadIdx.x & 31;
    int base = row & ~511;
    int cnt = min(g_cnt[row], MAXDEG);
    float ag[FNN] = {0, 0, 0}, ad[FNN] = {0, 0, 0}, afd[FNN] = {0, 0, 0};
    for (int n = lane; n < cnt; n += 32) {
        int gc = base + g_adj[row][n];
        #pragma unroll
        for (int i = 0; i < FNN; i++) {
            ag[i]  += g_gam[i][gc];
            ad[i]  += g_df[i][gc];
            afd[i] += g_fdf[i][gc];
        }
    }
    #pragma unroll
    for (int i = 0; i < FNN; i++) {
        #pragma unroll
        for (int o = 16; o > 0; o >>= 1) {
            ag[i]  += __shfl_down_sync(0xffffffffu, ag[i], o);
            ad[i]  += __shfl_down_sync(0xffffffffu, ad[i], o);
            afd[i] += __shfl_down_sync(0xffffffffu, afd[i], o);
        }
    }
    if (lane == 0) {
        float w1 = g_wm1;
        float kap = g_kap[row];
        float degw = w1 * (float)cnt;
        float term = -3.f * kap;
        #pragma unroll
        for (int i = 0; i < FNN; i++) {
            float f = g_f[i][row];
            float gamma = g_gam[i][row];
            float df = g_df[i][row];
            float wf = w1 * g_af[i][row];
            float dgamma = gamma * degw - w1 * ag[i];
            float gfd = 0.5f * (f * df * degw - f * w1 * ad[i]
                                - df * wf + w1 * afd[i]);
            float gamma2 = 0.5f * dgamma - gfd;
            term += fmaxf(kap * gamma - gamma2, 0.f);
        }
        g_term[row] = term;
    }
}

// ---------------- final loss sum ----------------
__global__ void k_loss(float* __restrict__ out) {
    __shared__ float red[512];
    int t = threadIdx.x;
    float acc = 0.f;
    #pragma unroll
    for (int i = t; i < BN; i += 512) acc += g_term[i];
    red[t] = acc;
    __syncthreads();
    for (int s = 256; s > 0; s >>= 1) { if (t < s) red[t] += red[t + s]; __syncthreads(); }
    if (t == 0) out[80] = red[0];
}

// ---------------- fused GIN layer: agg + 2-layer MLP, tiled 16 rows/block ----------------
// grid 256, block 256
__global__ void k_gin(const float* __restrict__ hin, int Din,
                      const float* __restrict__ gin_eps, const int* __restrict__ p, int layer,
                      const float* __restrict__ W1, const float* __restrict__ b1,
                      const float* __restrict__ W2, const float* __restrict__ b2,
                      float* __restrict__ hout) {
    __shared__ float sW[128 * 64];   // stage1: W1 (Din*64); stage2: W2 (64*64)
    __shared__ float sX[16 * 128];
    __shared__ float sH[16 * 68];
    int row0 = blockIdx.x * 16;
    int t = threadIdx.x;
    for (int i = t; i < Din * 16; i += 256) ((float4*)sW)[i] = ((const float4*)W1)[i];
    // ---- aggregation: sX[r][d] = (1+eps)*h[row][d] + sum_{alive nbrs} h[nbr][d]
    float eps = gin_eps[layer];
    int cut = (512 * p[0] * layer) / 100;
    int w = t >> 5, lane = t & 31;
    #pragma unroll
    for (int rr = 0; rr < 2; rr++) {
        int r = w * 2 + rr;
        int row = row0 + r;
        int base = row & ~511;
        bool alive = g_rank[row] >= cut;
        int cnt = min(g_cnt[row], MAXDEG);
        float acc[4] = {0, 0, 0, 0};
        if (alive) {
            for (int n = 0; n < cnt; n++) {
                int gc = base + g_adj[row][n];
                if (g_rank[gc] >= cut) {
                    const float* hr = hin + (size_t)gc * Din;
                    #pragma unroll
                    for (int k = 0; k < 4; k++) {
                        int d = lane + 32 * k;
                        if (d < Din) acc[k] += hr[d];
                    }
                }
            }
        }
        const float* hr = hin + (size_t)row * Din;
        #pragma unroll
        for (int k = 0; k < 4; k++) {
            int d = lane + 32 * k;
            if (d < Din) sX[r * 128 + d] = (1.f + eps) * hr[d] + acc[k];
        }
    }
    __syncthreads();
    // ---- layer 1: h1 = relu(agg @ W1 + b1)
    int hid = t & 63, rsub = t >> 6;
    float b1v = b1[hid];
    #pragma unroll
    for (int pass = 0; pass < 4; pass++) {
        int r = pass * 4 + rsub;
        float a = b1v;
        const float* xr = sX + r * 128;
        for (int d = 0; d < Din; d++) a = fmaf(xr[d], sW[d * 64 + hid], a);
        sH[r * 68 + hid] = fmaxf(a, 0.f);
    }
    __syncthreads();
    // ---- swap W2 into sW
    for (int i = t; i < 1024; i += 256) ((float4*)sW)[i] = ((const float4*)W2)[i];
    float b2v = b2[hid];
    __syncthreads();
    // ---- layer 2: h = relu(h1 @ W2 + b2)
    #pragma unroll
    for (int pass = 0; pass < 4; pass++) {
        int r = pass * 4 + rsub;
        float a = b2v;
        const float* hr2 = sH + r * 68;
        #pragma unroll 16
        for (int k = 0; k < 64; k++) a = fmaf(hr2[k], sW[k * 64 + hid], a);
        hout[(size_t)(row0 + r) * 64 + hid] = fmaxf(a, 0.f);
    }
}

// ---------------- readout ----------------
__global__ void k_out(const float* __restrict__ X, const float* __restrict__ oW,
                      const float* __restrict__ ob, float* __restrict__ out) {
    __shared__ float S[320];
    int b = blockIdx.x, c = threadIdx.x;
    float acc = 0.f;
    if (c < 128) {
        const float* base = X + ((size_t)b * 512) * 128 + c;
        for (int n = 0; n < 512; n++) acc += base[n * 128];
    } else {
        int l = (c - 128) / 64, cc = (c - 128) % 64;
        const float* base = g_h[l] + ((size_t)b * 512) * 64 + cc;
        for (int n = 0; n < 512; n++) acc += base[n * 64];
    }
    S[c] = acc;
    __syncthreads();
    if (c < 10) {
        float o = ob[c];
        for (int k = 0; k < 320; k++) o = fmaf(S[k], oW[k * 10 + c], o);
        out[b * 10 + c] = o;
    }
}

// ---------------- launch ----------------
extern "C" void kernel_launch(void* const* d_in, const int* in_sizes, int n_in,
                              void* d_out, int out_size) {
    const float* X    = (const float*)d_in[0];
    const float* A    = (const float*)d_in[1];
    const int*   p    = (const int*)  d_in[2];
    const float* cW1  = (const float*)d_in[3];
    const float* cb1  = (const float*)d_in[4];
    const float* cW2  = (const float*)d_in[5];
    const float* cb2  = (const float*)d_in[6];
    const float* wmW1 = (const float*)d_in[7];
    const float* wmb1 = (const float*)d_in[8];
    const float* wmW2 = (const float*)d_in[9];
    const float* wmb2 = (const float*)d_in[10];
    const float* wmW3 = (const float*)d_in[11];
    const float* wmb3 = (const float*)d_in[12];
    const float* fnW1 = (const float*)d_in[13];
    const float* fnb1 = (const float*)d_in[14];
    const float* fnW2 = (const float*)d_in[15];
    const float* fnb2 = (const float*)d_in[16];
    const float* eps  = (const float*)d_in[17];
    const float* g0W1 = (const float*)d_in[18];
    const float* g0b1 = (const float*)d_in[19];
    const float* g0W2 = (const float*)d_in[20];
    const float* g0b2 = (const float*)d_in[21];
    const float* g1W1 = (const float*)d_in[22];
    const float* g1b1 = (const float*)d_in[23];
    const float* g1W2 = (const float*)d_in[24];
    const float* g1b2 = (const float*)d_in[25];
    const float* g2W1 = (const float*)d_in[26];
    const float* g2b1 = (const float*)d_in[27];
    const float* g2W2 = (const float*)d_in[28];
    const float* g2b2 = (const float*)d_in[29];
    const float* oW   = (const float*)d_in[30];
    const float* ob   = (const float*)d_in[31];
    float* out = (float*)d_out;

    float* h0 = nullptr; float* h1 = nullptr; float* h2 = nullptr;
    cudaGetSymbolAddress((void**)&h0, g_h);   // base of g_h[0]
    h1 = h0 + (size_t)BN * HH;
    h2 = h0 + (size_t)2 * BN * HH;

    k_wm1 <<<1, 64>>>(wmW1, wmb1, wmW2, wmb2, wmW3, wmb3);
    k_adj <<<2048, 256>>>(A);
    k_node<<<dim3(256, 4), 256>>>(X, cW1, cb1, cW2, cb2, fnW1, fnb1, fnW2, fnb2);
    k_rank<<<8, 512>>>();
    k_spmv1<<<1024, 128>>>();
    k_spmv2<<<1024, 128>>>();
    k_loss<<<1, 512>>>(out);

    k_gin<<<256, 256>>>(X,  128, eps, p, 0, g0W1, g0b1, g0W2, g0b2, h0);
    k_gin<<<256, 256>>>(h0,  64, eps, p, 1, g1W1, g1b1, g1W2, g1b2, h1);
    k_gin<<<256, 256>>>(h1,  64, eps, p, 2, g2W1, g2b1, g2W2, g2b2, h2);

    k_out<<<8, 320>>>(X, oW, ob, out);
}

// round 3
// speedup vs baseline: 1.2350x; 1.2350x over previous
#include <cuda_runtime.h>
#include <math.h>

#define BB   8
#define NN   512
#define DD   128
#define HH   64
#define FNN  3
#define BN   4096
#define MAXDEG 192

// ---------------- device scratch ----------------
__device__ float g_wm1;
__device__ float g_kap[BN];
__device__ float g_f[FNN][BN];
__device__ int   g_rank[BN];
__device__ int   g_cnt[BN];
__device__ int   g_adj[BN][MAXDEG];
__device__ float g_af[FNN][BN];
__device__ float g_gam[FNN][BN], g_df[FNN][BN], g_fdf[FNN][BN];
__device__ float g_term[BN];
__device__ float g_h[3][BN * HH];

// packed dual-fp32 FMA (sm_103a FFMA2)
__device__ __forceinline__ float2 ffma2(float2 a, float2 b, float2 c) {
    union U { float2 f; unsigned long long u; } ua, ub, uc, ud;
    ua.f = a; ub.f = b; uc.f = c;
    asm("fma.rn.f32x2 %0, %1, %2, %3;" : "=l"(ud.u) : "l"(ua.u), "l"(ub.u), "l"(uc.u));
    return ud.f;
}

// ---------------- CSR build (blocks 0..2047) + wm1 scalar (block 2048) ----------------
__global__ void k_adj(const float* __restrict__ A,
                      const float* __restrict__ W1, const float* __restrict__ b1,
                      const float* __restrict__ W2, const float* __restrict__ b2,
                      const float* __restrict__ W3, const float* __restrict__ b3) {
    if (blockIdx.x == 2048) {              // weight-MLP(1.0) scalar
        __shared__ float h1[64], h2[32];
        int t = threadIdx.x;
        if (t < 64) h1[t] = fmaxf(W1[t] + b1[t], 0.f);
        __syncthreads();
        if (t < 32) {
            float s = b2[t];
            for (int k = 0; k < 64; k++) s = fmaf(h1[k], W2[k * 32 + t], s);
            h2[t] = fmaxf(s, 0.f);
        }
        __syncthreads();
        if (t == 0) {
            float s = b3[0];
            for (int k = 0; k < 32; k++) s = fmaf(h2[k], W3[k], s);
            g_wm1 = 1.f / (1.f + expf(-s));
        }
        return;
    }
    int r2 = threadIdx.x >> 7;
    int row = blockIdx.x * 2 + r2;
    int t = threadIdx.x & 127;
    int lane = threadIdx.x & 31;
    int w = (threadIdx.x >> 5) & 3;
    float4 v = ((const float4*)(A + (size_t)row * 512))[t];
    unsigned flags = (v.x != 0.f ? 1u : 0u) | (v.y != 0.f ? 2u : 0u) |
                     (v.z != 0.f ? 4u : 0u) | (v.w != 0.f ? 8u : 0u);
    int c = __popc(flags);
    int sc = c;
    #pragma unroll
    for (int o = 1; o < 32; o <<= 1) {
        int n = __shfl_up_sync(0xffffffffu, sc, o);
        if (lane >= o) sc += n;
    }
    __shared__ int wsum[2][4];
    if (lane == 31) wsum[r2][w] = sc;
    __syncthreads();
    int wbase = 0;
    #pragma unroll
    for (int i = 0; i < 4; i++) if (i < w) wbase += wsum[r2][i];
    int off = wbase + sc - c;
    int col = t * 4;
    #pragma unroll
    for (int k = 0; k < 4; k++) {
        if ((flags >> k) & 1u) {
            if (off < MAXDEG) g_adj[row][off] = col + k;
            off++;
        }
    }
    if (t == 127) g_cnt[row] = wbase + sc;
}

// ---------------- per-node MLPs (kappa + f0..f2): 32 rows/block, FFMA2 ----------------
// grid 128, block 256, dyn smem 55424
__global__ void k_node(const float* __restrict__ X,
                       const float* __restrict__ cW1, const float* __restrict__ cb1,
                       const float* __restrict__ cW2, const float* __restrict__ cb2,
                       const float* __restrict__ fW1, const float* __restrict__ fb1,
                       const float* __restrict__ fW2, const float* __restrict__ fb2) {
    extern __shared__ float sm[];
    float* sW = sm;                 // 128*64
    float* xT = sW + 128 * 64;      // 128*36 (transposed X tile, padded)
    float* sP = xT + 128 * 36;      // 32*33 partials
    int t = threadIdx.x;
    int row0 = blockIdx.x * 32;
    // load X tile transposed: xT[d*36 + r] = X[row0+r][d]
    #pragma unroll
    for (int k = 0; k < 4; k++) {
        int i = t + k * 256;
        float4 v = ((const float4*)(X + (size_t)row0 * 128))[i];
        int li = i * 4;
        int r = li >> 7, d = li & 127;
        xT[(d + 0) * 36 + r] = v.x;
        xT[(d + 1) * 36 + r] = v.y;
        xT[(d + 2) * 36 + r] = v.z;
        xT[(d + 3) * 36 + r] = v.w;
    }
    int hp = t & 31, rq = t >> 5;
    for (int m = 0; m < 4; m++) {
        const float* W1 = (m == 0) ? cW1 : fW1 + (m - 1) * 8192;
        const float* b1 = (m == 0) ? cb1 : fb1 + (m - 1) * 64;
        const float* W2 = (m == 0) ? cW2 : fW2 + (m - 1) * 64;
        __syncthreads();                       // protect sW/sP from previous iter
        for (int i = t; i < 2048; i += 256) ((float4*)sW)[i] = ((const float4*)W1)[i];
        __syncthreads();
        float2 a00 = make_float2(0.f, 0.f), a01 = a00, a10 = a00, a11 = a00;
        #pragma unroll 4
        for (int d = 0; d < 128; d++) {
            float2 wv = *(const float2*)&sW[d * 64 + hp * 2];
            float4 xv = *(const float4*)&xT[d * 36 + rq * 4];
            float2 x01 = make_float2(xv.x, xv.y), x23 = make_float2(xv.z, xv.w);
            float2 w0 = make_float2(wv.x, wv.x), w1 = make_float2(wv.y, wv.y);
            a00 = ffma2(x01, w0, a00); a01 = ffma2(x23, w0, a01);
            a10 = ffma2(x01, w1, a10); a11 = ffma2(x23, w1, a11);
        }
        float b10 = b1[hp * 2], b11 = b1[hp * 2 + 1];
        float w20 = W2[hp * 2], w21 = W2[hp * 2 + 1];
        int rb = rq * 4;
        sP[(rb + 0) * 33 + hp] = fmaxf(a00.x + b10, 0.f) * w20 + fmaxf(a10.x + b11, 0.f) * w21;
        sP[(rb + 1) * 33 + hp] = fmaxf(a00.y + b10, 0.f) * w20 + fmaxf(a10.y + b11, 0.f) * w21;
        sP[(rb + 2) * 33 + hp] = fmaxf(a01.x + b10, 0.f) * w20 + fmaxf(a11.x + b11, 0.f) * w21;
        sP[(rb + 3) * 33 + hp] = fmaxf(a01.y + b10, 0.f) * w20 + fmaxf(a11.y + b11, 0.f) * w21;
        __syncthreads();
        if (t < 32) {
            float s = (m == 0) ? cb2[0] : fb2[m - 1];
            const float* pr = &sP[t * 33];
            #pragma unroll
            for (int k = 0; k < 32; k++) s += pr[k];
            float v = 1.f / (1.f + expf(-s));
            if (m == 0) g_kap[row0 + t] = v; else g_f[m - 1][row0 + t] = v;
        }
    }
}

// ---------------- rank by counting (matches top_k tie-break) ----------------
// grid (8,4), block 128
__global__ void k_rank() {
    __shared__ float sv[512];
    int b = blockIdx.x, t = threadIdx.x;
    for (int i = t; i < 512; i += 128) sv[i] = g_kap[b * 512 + i];
    __syncthreads();
    int i = blockIdx.y * 128 + t;
    float vi = sv[i];
    int cnt = 0;
    #pragma unroll 8
    for (int j = 0; j < 512; j++) {
        float vj = sv[j];
        cnt += (vj > vi) || (vj == vi && j < i);
    }
    g_rank[b * 512 + i] = cnt;
}

// ---------------- spmv1 (A@f, A@f^2) + fused gamma/df/fdf ----------------
// grid 512, block 256 (8 rows/block)
__global__ void k_spmv1() {
    int row = blockIdx.x * 8 + (threadIdx.x >> 5);
    int lane = threadIdx.x & 31;
    int base = row & ~511;
    int cnt = min(g_cnt[row], MAXDEG);
    float af[FNN] = {0, 0, 0}, aq[FNN] = {0, 0, 0};
    for (int n = lane; n < cnt; n += 32) {
        int gc = base + g_adj[row][n];
        #pragma unroll
        for (int i = 0; i < FNN; i++) {
            float fv = g_f[i][gc];
            af[i] += fv; aq[i] += fv * fv;
        }
    }
    #pragma unroll
    for (int i = 0; i < FNN; i++) {
        #pragma unroll
        for (int o = 16; o > 0; o >>= 1) {
            af[i] += __shfl_down_sync(0xffffffffu, af[i], o);
            aq[i] += __shfl_down_sync(0xffffffffu, aq[i], o);
        }
    }
    if (lane == 0) {
        float w1 = g_wm1;
        float degw = w1 * (float)cnt;
        #pragma unroll
        for (int i = 0; i < FNN; i++) {
            float f = g_f[i][row];
            float wf = w1 * af[i];
            float gamma = 0.5f * (f * f * degw - 2.f * f * wf + w1 * aq[i]);
            float df = f * degw - wf;
            g_af[i][row] = af[i];
            g_gam[i][row] = gamma; g_df[i][row] = df; g_fdf[i][row] = f * df;
        }
    }
}

// ---------------- spmv2 + per-row loss term ----------------
__global__ void k_spmv2() {
    int row = blockIdx.x * 8 + (threadIdx.x >> 5);
    int lane = threadIdx.x & 31;
    int base = row & ~511;
    int cnt = min(g_cnt[row], MAXDEG);
    float ag[FNN] = {0, 0, 0}, ad[FNN] = {0, 0, 0}, afd[FNN] = {0, 0, 0};
    for (int n = lane; n < cnt; n += 32) {
        int gc = base + g_adj[row][n];
        #pragma unroll
        for (int i = 0; i < FNN; i++) {
            ag[i]  += g_gam[i][gc];
            ad[i]  += g_df[i][gc];
            afd[i] += g_fdf[i][gc];
        }
    }
    #pragma unroll
    for (int i = 0; i < FNN; i++) {
        #pragma unroll
        for (int o = 16; o > 0; o >>= 1) {
            ag[i]  += __shfl_down_sync(0xffffffffu, ag[i], o);
            ad[i]  += __shfl_down_sync(0xffffffffu, ad[i], o);
            afd[i] += __shfl_down_sync(0xffffffffu, afd[i], o);
        }
    }
    if (lane == 0) {
        float w1 = g_wm1;
        float kap = g_kap[row];
        float degw = w1 * (float)cnt;
        float term = -3.f * kap;
        #pragma unroll
        for (int i = 0; i < FNN; i++) {
            float f = g_f[i][row];
            float gamma = g_gam[i][row];
            float df = g_df[i][row];
            float wf = w1 * g_af[i][row];
            float dgamma = gamma * degw - w1 * ag[i];
            float gfd = 0.5f * (f * df * degw - f * w1 * ad[i]
                                - df * wf + w1 * afd[i]);
            float gamma2 = 0.5f * dgamma - gfd;
            term += fmaxf(kap * gamma - gamma2, 0.f);
        }
        g_term[row] = term;
    }
}

// ---------------- fused GIN layer: agg + 2-layer MLP (FFMA2), 32 rows/block ----------------
// grid 128, block 256, dyn smem
template <int DIN>
__global__ void k_gin(const float* __restrict__ hin,
                      const float* __restrict__ gin_eps, const int* __restrict__ p, int layer,
                      const float* __restrict__ W1, const float* __restrict__ b1,
                      const float* __restrict__ W2, const float* __restrict__ b2,
                      float* __restrict__ hout) {
    extern __shared__ float sm[];
    float* sW1 = sm;                   // DIN*64
    float* sW2 = sW1 + DIN * 64;       // 64*64
    float* xT  = sW2 + 64 * 64;        // DIN*36
    float* hT  = xT + DIN * 36;        // 64*36
    int t = threadIdx.x;
    int row0 = blockIdx.x * 32;
    for (int i = t; i < DIN * 16; i += 256) ((float4*)sW1)[i] = ((const float4*)W1)[i];
    for (int i = t; i < 1024;     i += 256) ((float4*)sW2)[i] = ((const float4*)W2)[i];
    // ---- aggregation into xT (transposed)
    float c1 = 1.f + gin_eps[layer];
    int cut = (512 * p[0] * layer) / 100;
    int w = t >> 5, lane = t & 31;
    const int KR = DIN / 32;
    #pragma unroll
    for (int rr = 0; rr < 4; rr++) {
        int r = w * 4 + rr;
        int row = row0 + r;
        int base = row & ~511;
        int cnt = min(g_cnt[row], MAXDEG);
        bool alive = g_rank[row] >= cut;
        float acc[KR];
        #pragma unroll
        for (int k = 0; k < KR; k++) acc[k] = 0.f;
        if (alive) {
            for (int n = 0; n < cnt; n++) {
                int gc = base + g_adj[row][n];
                if (g_rank[gc] >= cut) {
                    const float* hr = hin + (size_t)gc * DIN;
                    #pragma unroll
                    for (int k = 0; k < KR; k++) acc[k] += hr[lane + 32 * k];
                }
            }
        }
        const float* hr = hin + (size_t)row * DIN;
        #pragma unroll
        for (int k = 0; k < KR; k++) {
            int d = lane + 32 * k;
            xT[d * 36 + r] = fmaf(c1, hr[d], acc[k]);
        }
    }
    __syncthreads();
    // ---- MLP layer 1
    int hp = t & 31, rq = t >> 5;
    {
        float2 a00 = make_float2(0.f, 0.f), a01 = a00, a10 = a00, a11 = a00;
        #pragma unroll 4
        for (int d = 0; d < DIN; d++) {
            float2 wv = *(const float2*)&sW1[d * 64 + hp * 2];
            float4 xv = *(const float4*)&xT[d * 36 + rq * 4];
            float2 x01 = make_float2(xv.x, xv.y), x23 = make_float2(xv.z, xv.w);
            float2 w0 = make_float2(wv.x, wv.x), w1 = make_float2(wv.y, wv.y);
            a00 = ffma2(x01, w0, a00); a01 = ffma2(x23, w0, a01);
            a10 = ffma2(x01, w1, a10); a11 = ffma2(x23, w1, a11);
        }
        float b10 = b1[hp * 2], b11 = b1[hp * 2 + 1];
        int rb = rq * 4;
        hT[(hp * 2) * 36 + rb + 0] = fmaxf(a00.x + b10, 0.f);
        hT[(hp * 2) * 36 + rb + 1] = fmaxf(a00.y + b10, 0.f);
        hT[(hp * 2) * 36 + rb + 2] = fmaxf(a01.x + b10, 0.f);
        hT[(hp * 2) * 36 + rb + 3] = fmaxf(a01.y + b10, 0.f);
        hT[(hp * 2 + 1) * 36 + rb + 0] = fmaxf(a10.x + b11, 0.f);
        hT[(hp * 2 + 1) * 36 + rb + 1] = fmaxf(a10.y + b11, 0.f);
        hT[(hp * 2 + 1) * 36 + rb + 2] = fmaxf(a11.x + b11, 0.f);
        hT[(hp * 2 + 1) * 36 + rb + 3] = fmaxf(a11.y + b11, 0.f);
    }
    __syncthreads();
    // ---- MLP layer 2
    {
        float2 a00 = make_float2(0.f, 0.f), a01 = a00, a10 = a00, a11 = a00;
        #pragma unroll 4
        for (int k = 0; k < 64; k++) {
            float2 wv = *(const float2*)&sW2[k * 64 + hp * 2];
            float4 xv = *(const float4*)&hT[k * 36 + rq * 4];
            float2 x01 = make_float2(xv.x, xv.y), x23 = make_float2(xv.z, xv.w);
            float2 w0 = make_float2(wv.x, wv.x), w1 = make_float2(wv.y, wv.y);
            a00 = ffma2(x01, w0, a00); a01 = ffma2(x23, w0, a01);
            a10 = ffma2(x01, w1, a10); a11 = ffma2(x23, w1, a11);
        }
        float b20 = b2[hp * 2], b21 = b2[hp * 2 + 1];
        int rb = rq * 4;
        float* o0 = hout + (size_t)(row0 + rb + 0) * 64 + hp * 2;
        float* o1 = hout + (size_t)(row0 + rb + 1) * 64 + hp * 2;
        float* o2 = hout + (size_t)(row0 + rb + 2) * 64 + hp * 2;
        float* o3 = hout + (size_t)(row0 + rb + 3) * 64 + hp * 2;
        *(float2*)o0 = make_float2(fmaxf(a00.x + b20, 0.f), fmaxf(a10.x + b21, 0.f));
        *(float2*)o1 = make_float2(fmaxf(a00.y + b20, 0.f), fmaxf(a10.y + b21, 0.f));
        *(float2*)o2 = make_float2(fmaxf(a01.x + b20, 0.f), fmaxf(a11.x + b21, 0.f));
        *(float2*)o3 = make_float2(fmaxf(a01.y + b20, 0.f), fmaxf(a11.y + b21, 0.f));
    }
}

// ---------------- readout (blocks 0..7) + loss reduce (block 8) ----------------
__global__ void k_out(const float* __restrict__ X, const float* __restrict__ oW,
                      const float* __restrict__ ob, float* __restrict__ out) {
    if (blockIdx.x == 8) {
        __shared__ float red[256];
        int t = threadIdx.x;
        if (t < 256) {
            float a0 = 0.f, a1 = 0.f, a2 = 0.f, a3 = 0.f;
            for (int i = t * 4; i < BN; i += 1024) {
                a0 += g_term[i]; a1 += g_term[i + 1]; a2 += g_term[i + 2]; a3 += g_term[i + 3];
            }
            red[t] = (a0 + a1) + (a2 + a3);
        }
        __syncthreads();
        for (int s = 128; s > 0; s >>= 1) { if (t < s) red[t] += red[t + s]; __syncthreads(); }
        if (t == 0) out[80] = red[0];
        return;
    }
    __shared__ float S[320];
    int b = blockIdx.x, c = threadIdx.x;
    float a0 = 0.f, a1 = 0.f, a2 = 0.f, a3 = 0.f;
    if (c < 128) {
        const float* base = X + ((size_t)b * 512) * 128 + c;
        for (int n = 0; n < 512; n += 4) {
            a0 += base[n * 128]; a1 += base[(n + 1) * 128];
            a2 += base[(n + 2) * 128]; a3 += base[(n + 3) * 128];
        }
    } else {
        int l = (c - 128) / 64, cc = (c - 128) % 64;
        const float* base = g_h[l] + ((size_t)b * 512) * 64 + cc;
        for (int n = 0; n < 512; n += 4) {
            a0 += base[n * 64]; a1 += base[(n + 1) * 64];
            a2 += base[(n + 2) * 64]; a3 += base[(n + 3) * 64];
        }
    }
    S[c] = (a0 + a1) + (a2 + a3);
    __syncthreads();
    if (c < 10) {
        float o = ob[c];
        for (int k = 0; k < 320; k++) o = fmaf(S[k], oW[k * 10 + c], o);
        out[b * 10 + c] = o;
    }
}

// ---------------- launch ----------------
extern "C" void kernel_launch(void* const* d_in, const int* in_sizes, int n_in,
                              void* d_out, int out_size) {
    const float* X    = (const float*)d_in[0];
    const float* A    = (const float*)d_in[1];
    const int*   p    = (const int*)  d_in[2];
    const float* cW1  = (const float*)d_in[3];
    const float* cb1  = (const float*)d_in[4];
    const float* cW2  = (const float*)d_in[5];
    const float* cb2  = (const float*)d_in[6];
    const float* wmW1 = (const float*)d_in[7];
    const float* wmb1 = (const float*)d_in[8];
    const float* wmW2 = (const float*)d_in[9];
    const float* wmb2 = (const float*)d_in[10];
    const float* wmW3 = (const float*)d_in[11];
    const float* wmb3 = (const float*)d_in[12];
    const float* fnW1 = (const float*)d_in[13];
    const float* fnb1 = (const float*)d_in[14];
    const float* fnW2 = (const float*)d_in[15];
    const float* fnb2 = (const float*)d_in[16];
    const float* eps  = (const float*)d_in[17];
    const float* g0W1 = (const float*)d_in[18];
    const float* g0b1 = (const float*)d_in[19];
    const float* g0W2 = (const float*)d_in[20];
    const float* g0b2 = (const float*)d_in[21];
    const float* g1W1 = (const float*)d_in[22];
    const float* g1b1 = (const float*)d_in[23];
    const float* g1W2 = (const float*)d_in[24];
    const float* g1b2 = (const float*)d_in[25];
    const float* g2W1 = (const float*)d_in[26];
    const float* g2b1 = (const float*)d_in[27];
    const float* g2W2 = (const float*)d_in[28];
    const float* g2b2 = (const float*)d_in[29];
    const float* oW   = (const float*)d_in[30];
    const float* ob   = (const float*)d_in[31];
    float* out = (float*)d_out;

    float* h0 = nullptr;
    cudaGetSymbolAddress((void**)&h0, g_h);
    float* h1 = h0 + (size_t)BN * HH;
    float* h2 = h0 + (size_t)2 * BN * HH;

    const int SM_NODE  = (128 * 64 + 128 * 36 + 32 * 33) * 4;            // 55424
    const int SM_GIN0  = (128 * 64 + 64 * 64 + 128 * 36 + 64 * 36) * 4;  // 76800
    const int SM_GIN1  = (64 * 64 + 64 * 64 + 64 * 36 + 64 * 36) * 4;    // 51200
    cudaFuncSetAttribute(k_node,    cudaFuncAttributeMaxDynamicSharedMemorySize, SM_NODE);
    cudaFuncSetAttribute(k_gin<128>, cudaFuncAttributeMaxDynamicSharedMemorySize, SM_GIN0);
    cudaFuncSetAttribute(k_gin<64>,  cudaFuncAttributeMaxDynamicSharedMemorySize, SM_GIN1);

    k_adj <<<2049, 256>>>(A, wmW1, wmb1, wmW2, wmb2, wmW3, wmb3);
    k_node<<<128, 256, SM_NODE>>>(X, cW1, cb1, cW2, cb2, fnW1, fnb1, fnW2, fnb2);
    k_rank<<<dim3(8, 4), 128>>>();
    k_spmv1<<<512, 256>>>();
    k_spmv2<<<512, 256>>>();

    k_gin<128><<<128, 256, SM_GIN0>>>(X,  eps, p, 0, g0W1, g0b1, g0W2, g0b2, h0);
    k_gin<64> <<<128, 256, SM_GIN1>>>(h0, eps, p, 1, g1W1, g1b1, g1W2, g1b2, h1);
    k_gin<64> <<<128, 256, SM_GIN1>>>(h1, eps, p, 2, g2W1, g2b1, g2W2, g2b2, h2);

    k_out<<<9, 320>>>(X, oW, ob, out);
}

// round 4
// speedup vs baseline: 1.2384x; 1.0028x over previous
#include <cuda_runtime.h>
#include <math.h>

#define BB   8
#define NN   512
#define DD   128
#define HH   64
#define FNN  3
#define BN   4096
#define MAXDEG 192

// ---------------- device scratch ----------------
__device__ float g_wm1;
__device__ float g_kap[BN];
__device__ float g_f[FNN][BN];
__device__ int   g_rank[BN];
__device__ int   g_cnt[BN];
__device__ int   g_adj[BN][MAXDEG];
__device__ float g_af[FNN][BN];
__device__ float g_gam[FNN][BN], g_df[FNN][BN], g_fdf[FNN][BN];
__device__ float g_term[BN];
__device__ float g_h[3][BN * HH];

// packed dual-fp32 FMA (sm_103a FFMA2)
__device__ __forceinline__ float2 ffma2(float2 a, float2 b, float2 c) {
    union U { float2 f; unsigned long long u; } ua, ub, uc, ud;
    ua.f = a; ub.f = b; uc.f = c;
    asm("fma.rn.f32x2 %0, %1, %2, %3;" : "=l"(ud.u) : "l"(ua.u), "l"(ub.u), "l"(uc.u));
    return ud.f;
}

// ---------------- CSR build (blocks 0..2047) + wm1 scalar (block 2048) ----------------
__global__ void k_adj(const float* __restrict__ A,
                      const float* __restrict__ W1, const float* __restrict__ b1,
                      const float* __restrict__ W2, const float* __restrict__ b2,
                      const float* __restrict__ W3, const float* __restrict__ b3) {
    if (blockIdx.x == 2048) {              // weight-MLP(1.0) scalar
        __shared__ float h1[64], h2[32];
        int t = threadIdx.x;
        if (t < 64) h1[t] = fmaxf(W1[t] + b1[t], 0.f);
        __syncthreads();
        if (t < 32) {
            float s = b2[t];
            for (int k = 0; k < 64; k++) s = fmaf(h1[k], W2[k * 32 + t], s);
            h2[t] = fmaxf(s, 0.f);
        }
        __syncthreads();
        if (t == 0) {
            float s = b3[0];
            for (int k = 0; k < 32; k++) s = fmaf(h2[k], W3[k], s);
            g_wm1 = 1.f / (1.f + expf(-s));
        }
        return;
    }
    int r2 = threadIdx.x >> 7;
    int row = blockIdx.x * 2 + r2;
    int t = threadIdx.x & 127;
    int lane = threadIdx.x & 31;
    int w = (threadIdx.x >> 5) & 3;
    float4 v = ((const float4*)(A + (size_t)row * 512))[t];
    unsigned flags = (v.x != 0.f ? 1u : 0u) | (v.y != 0.f ? 2u : 0u) |
                     (v.z != 0.f ? 4u : 0u) | (v.w != 0.f ? 8u : 0u);
    int c = __popc(flags);
    int sc = c;
    #pragma unroll
    for (int o = 1; o < 32; o <<= 1) {
        int n = __shfl_up_sync(0xffffffffu, sc, o);
        if (lane >= o) sc += n;
    }
    __shared__ int wsum[2][4];
    if (lane == 31) wsum[r2][w] = sc;
    __syncthreads();
    int wbase = 0;
    #pragma unroll
    for (int i = 0; i < 4; i++) if (i < w) wbase += wsum[r2][i];
    int off = wbase + sc - c;
    int col = t * 4;
    #pragma unroll
    for (int k = 0; k < 4; k++) {
        if ((flags >> k) & 1u) {
            if (off < MAXDEG) g_adj[row][off] = col + k;
            off++;
        }
    }
    if (t == 127) g_cnt[row] = wbase + sc;
}

// ---------------- per-node MLPs (kappa + f0..f2): 32 rows/block, FFMA2 ----------------
// grid 128, block 256, dyn smem 55424
__global__ void k_node(const float* __restrict__ X,
                       const float* __restrict__ cW1, const float* __restrict__ cb1,
                       const float* __restrict__ cW2, const float* __restrict__ cb2,
                       const float* __restrict__ fW1, const float* __restrict__ fb1,
                       const float* __restrict__ fW2, const float* __restrict__ fb2) {
    extern __shared__ float sm[];
    float* sW = sm;                 // 128*64
    float* xT = sW + 128 * 64;      // 128*36 (transposed X tile, padded)
    float* sP = xT + 128 * 36;      // 32*33 partials
    int t = threadIdx.x;
    int row0 = blockIdx.x * 32;
    // load X tile transposed: xT[d*36 + r] = X[row0+r][d]
    #pragma unroll
    for (int k = 0; k < 4; k++) {
        int i = t + k * 256;
        float4 v = ((const float4*)(X + (size_t)row0 * 128))[i];
        int li = i * 4;
        int r = li >> 7, d = li & 127;
        xT[(d + 0) * 36 + r] = v.x;
        xT[(d + 1) * 36 + r] = v.y;
        xT[(d + 2) * 36 + r] = v.z;
        xT[(d + 3) * 36 + r] = v.w;
    }
    int hp = t & 31, rq = t >> 5;
    for (int m = 0; m < 4; m++) {
        const float* W1 = (m == 0) ? cW1 : fW1 + (m - 1) * 8192;
        const float* b1 = (m == 0) ? cb1 : fb1 + (m - 1) * 64;
        const float* W2 = (m == 0) ? cW2 : fW2 + (m - 1) * 64;
        __syncthreads();                       // protect sW/sP from previous iter
        for (int i = t; i < 2048; i += 256) ((float4*)sW)[i] = ((const float4*)W1)[i];
        __syncthreads();
        float2 a00 = make_float2(0.f, 0.f), a01 = a00, a10 = a00, a11 = a00;
        #pragma unroll 4
        for (int d = 0; d < 128; d++) {
            float2 wv = *(const float2*)&sW[d * 64 + hp * 2];
            float4 xv = *(const float4*)&xT[d * 36 + rq * 4];
            float2 x01 = make_float2(xv.x, xv.y), x23 = make_float2(xv.z, xv.w);
            float2 w0 = make_float2(wv.x, wv.x), w1 = make_float2(wv.y, wv.y);
            a00 = ffma2(x01, w0, a00); a01 = ffma2(x23, w0, a01);
            a10 = ffma2(x01, w1, a10); a11 = ffma2(x23, w1, a11);
        }
        float b10 = b1[hp * 2], b11 = b1[hp * 2 + 1];
        float w20 = W2[hp * 2], w21 = W2[hp * 2 + 1];
        int rb = rq * 4;
        sP[(rb + 0) * 33 + hp] = fmaxf(a00.x + b10, 0.f) * w20 + fmaxf(a10.x + b11, 0.f) * w21;
        sP[(rb + 1) * 33 + hp] = fmaxf(a00.y + b10, 0.f) * w20 + fmaxf(a10.y + b11, 0.f) * w21;
        sP[(rb + 2) * 33 + hp] = fmaxf(a01.x + b10, 0.f) * w20 + fmaxf(a11.x + b11, 0.f) * w21;
        sP[(rb + 3) * 33 + hp] = fmaxf(a01.y + b10, 0.f) * w20 + fmaxf(a11.y + b11, 0.f) * w21;
        __syncthreads();
        if (t < 32) {
            float s = (m == 0) ? cb2[0] : fb2[m - 1];
            const float* pr = &sP[t * 33];
            #pragma unroll
            for (int k = 0; k < 32; k++) s += pr[k];
            float v = 1.f / (1.f + expf(-s));
            if (m == 0) g_kap[row0 + t] = v; else g_f[m - 1][row0 + t] = v;
        }
    }
}

// ---------------- rank by counting (matches top_k tie-break) ----------------
// grid (8,4), block 128
__global__ void k_rank() {
    __shared__ float sv[512];
    int b = blockIdx.x, t = threadIdx.x;
    for (int i = t; i < 512; i += 128) sv[i] = g_kap[b * 512 + i];
    __syncthreads();
    int i = blockIdx.y * 128 + t;
    float vi = sv[i];
    int cnt = 0;
    #pragma unroll 8
    for (int j = 0; j < 512; j++) {
        float vj = sv[j];
        cnt += (vj > vi) || (vj == vi && j < i);
    }
    g_rank[b * 512 + i] = cnt;
}

// ---------------- spmv1 (A@f, A@f^2) + fused gamma/df/fdf ----------------
// grid 512, block 256 (8 rows/block)
__global__ void k_spmv1() {
    int row = blockIdx.x * 8 + (threadIdx.x >> 5);
    int lane = threadIdx.x & 31;
    int base = row & ~511;
    int cnt = min(g_cnt[row], MAXDEG);
    float af[FNN] = {0, 0, 0}, aq[FNN] = {0, 0, 0};
    for (int n = lane; n < cnt; n += 32) {
        int gc = base + g_adj[row][n];
        #pragma unroll
        for (int i = 0; i < FNN; i++) {
            float fv = g_f[i][gc];
            af[i] += fv; aq[i] += fv * fv;
        }
    }
    #pragma unroll
    for (int i = 0; i < FNN; i++) {
        #pragma unroll
        for (int o = 16; o > 0; o >>= 1) {
            af[i] += __shfl_down_sync(0xffffffffu, af[i], o);
            aq[i] += __shfl_down_sync(0xffffffffu, aq[i], o);
        }
    }
    if (lane == 0) {
        float w1 = g_wm1;
        float degw = w1 * (float)cnt;
        #pragma unroll
        for (int i = 0; i < FNN; i++) {
            float f = g_f[i][row];
            float wf = w1 * af[i];
            float gamma = 0.5f * (f * f * degw - 2.f * f * wf + w1 * aq[i]);
            float df = f * degw - wf;
            g_af[i][row] = af[i];
            g_gam[i][row] = gamma; g_df[i][row] = df; g_fdf[i][row] = f * df;
        }
    }
}

// ---------------- spmv2 + per-row loss term ----------------
__global__ void k_spmv2() {
    int row = blockIdx.x * 8 + (threadIdx.x >> 5);
    int lane = threadIdx.x & 31;
    int base = row & ~511;
    int cnt = min(g_cnt[row], MAXDEG);
    float ag[FNN] = {0, 0, 0}, ad[FNN] = {0, 0, 0}, afd[FNN] = {0, 0, 0};
    for (int n = lane; n < cnt; n += 32) {
        int gc = base + g_adj[row][n];
        #pragma unroll
        for (int i = 0; i < FNN; i++) {
            ag[i]  += g_gam[i][gc];
            ad[i]  += g_df[i][gc];
            afd[i] += g_fdf[i][gc];
        }
    }
    #pragma unroll
    for (int i = 0; i < FNN; i++) {
        #pragma unroll
        for (int o = 16; o > 0; o >>= 1) {
            ag[i]  += __shfl_down_sync(0xffffffffu, ag[i], o);
            ad[i]  += __shfl_down_sync(0xffffffffu, ad[i], o);
            afd[i] += __shfl_down_sync(0xffffffffu, afd[i], o);
        }
    }
    if (lane == 0) {
        float w1 = g_wm1;
        float kap = g_kap[row];
        float degw = w1 * (float)cnt;
        float term = -3.f * kap;
        #pragma unroll
        for (int i = 0; i < FNN; i++) {
            float f = g_f[i][row];
            float gamma = g_gam[i][row];
            float df = g_df[i][row];
            float wf = w1 * g_af[i][row];
            float dgamma = gamma * degw - w1 * ag[i];
            float gfd = 0.5f * (f * df * degw - f * w1 * ad[i]
                                - df * wf + w1 * afd[i]);
            float gamma2 = 0.5f * dgamma - gfd;
            term += fmaxf(kap * gamma - gamma2, 0.f);
        }
        g_term[row] = term;
    }
}

// ---------------- fused GIN layer: agg + 2-layer MLP (FFMA2), 32 rows/block ----------------
// grid 128, block 256, dyn smem
template <int DIN>
__global__ void k_gin(const float* __restrict__ hin,
                      const float* __restrict__ gin_eps, const int* __restrict__ p, int layer,
                      const float* __restrict__ W1, const float* __restrict__ b1,
                      const float* __restrict__ W2, const float* __restrict__ b2,
                      float* __restrict__ hout) {
    extern __shared__ float sm[];
    float* sW1 = sm;                   // DIN*64
    float* sW2 = sW1 + DIN * 64;       // 64*64
    float* xT  = sW2 + 64 * 64;        // DIN*36
    float* hT  = xT + DIN * 36;        // 64*36
    int t = threadIdx.x;
    int row0 = blockIdx.x * 32;
    for (int i = t; i < DIN * 16; i += 256) ((float4*)sW1)[i] = ((const float4*)W1)[i];
    for (int i = t; i < 1024;     i += 256) ((float4*)sW2)[i] = ((const float4*)W2)[i];
    // ---- aggregation into xT (transposed)
    float c1 = 1.f + gin_eps[layer];
    int cut = (512 * p[0] * layer) / 100;
    int w = t >> 5, lane = t & 31;
    const int KR = DIN / 32;
    #pragma unroll
    for (int rr = 0; rr < 4; rr++) {
        int r = w * 4 + rr;
        int row = row0 + r;
        int base = row & ~511;
        int cnt = min(g_cnt[row], MAXDEG);
        bool alive = g_rank[row] >= cut;
        float acc[KR];
        #pragma unroll
        for (int k = 0; k < KR; k++) acc[k] = 0.f;
        if (alive) {
            for (int n = 0; n < cnt; n++) {
                int gc = base + g_adj[row][n];
                if (g_rank[gc] >= cut) {
                    const float* hr = hin + (size_t)gc * DIN;
                    #pragma unroll
                    for (int k = 0; k < KR; k++) acc[k] += hr[lane + 32 * k];
                }
            }
        }
        const float* hr = hin + (size_t)row * DIN;
        #pragma unroll
        for (int k = 0; k < KR; k++) {
            int d = lane + 32 * k;
            xT[d * 36 + r] = fmaf(c1, hr[d], acc[k]);
        }
    }
    __syncthreads();
    // ---- MLP layer 1
    int hp = t & 31, rq = t >> 5;
    {
        float2 a00 = make_float2(0.f, 0.f), a01 = a00, a10 = a00, a11 = a00;
        #pragma unroll 4
        for (int d = 0; d < DIN; d++) {
            float2 wv = *(const float2*)&sW1[d * 64 + hp * 2];
            float4 xv = *(const float4*)&xT[d * 36 + rq * 4];
            float2 x01 = make_float2(xv.x, xv.y), x23 = make_float2(xv.z, xv.w);
            float2 w0 = make_float2(wv.x, wv.x), w1 = make_float2(wv.y, wv.y);
            a00 = ffma2(x01, w0, a00); a01 = ffma2(x23, w0, a01);
            a10 = ffma2(x01, w1, a10); a11 = ffma2(x23, w1, a11);
        }
        float b10 = b1[hp * 2], b11 = b1[hp * 2 + 1];
        int rb = rq * 4;
        hT[(hp * 2) * 36 + rb + 0] = fmaxf(a00.x + b10, 0.f);
        hT[(hp * 2) * 36 + rb + 1] = fmaxf(a00.y + b10, 0.f);
        hT[(hp * 2) * 36 + rb + 2] = fmaxf(a01.x + b10, 0.f);
        hT[(hp * 2) * 36 + rb + 3] = fmaxf(a01.y + b10, 0.f);
        hT[(hp * 2 + 1) * 36 + rb + 0] = fmaxf(a10.x + b11, 0.f);
        hT[(hp * 2 + 1) * 36 + rb + 1] = fmaxf(a10.y + b11, 0.f);
        hT[(hp * 2 + 1) * 36 + rb + 2] = fmaxf(a11.x + b11, 0.f);
        hT[(hp * 2 + 1) * 36 + rb + 3] = fmaxf(a11.y + b11, 0.f);
    }
    __syncthreads();
    // ---- MLP layer 2
    {
        float2 a00 = make_float2(0.f, 0.f), a01 = a00, a10 = a00, a11 = a00;
        #pragma unroll 4
        for (int k = 0; k < 64; k++) {
            float2 wv = *(const float2*)&sW2[k * 64 + hp * 2];
            float4 xv = *(const float4*)&hT[k * 36 + rq * 4];
            float2 x01 = make_float2(xv.x, xv.y), x23 = make_float2(xv.z, xv.w);
            float2 w0 = make_float2(wv.x, wv.x), w1 = make_float2(wv.y, wv.y);
            a00 = ffma2(x01, w0, a00); a01 = ffma2(x23, w0, a01);
            a10 = ffma2(x01, w1, a10); a11 = ffma2(x23, w1, a11);
        }
        float b20 = b2[hp * 2], b21 = b2[hp * 2 + 1];
        int rb = rq * 4;
        float* o0 = hout + (size_t)(row0 + rb + 0) * 64 + hp * 2;
        float* o1 = hout + (size_t)(row0 + rb + 1) * 64 + hp * 2;
        float* o2 = hout + (size_t)(row0 + rb + 2) * 64 + hp * 2;
        float* o3 = hout + (size_t)(row0 + rb + 3) * 64 + hp * 2;
        *(float2*)o0 = make_float2(fmaxf(a00.x + b20, 0.f), fmaxf(a10.x + b21, 0.f));
        *(float2*)o1 = make_float2(fmaxf(a00.y + b20, 0.f), fmaxf(a10.y + b21, 0.f));
        *(float2*)o2 = make_float2(fmaxf(a01.x + b20, 0.f), fmaxf(a11.x + b21, 0.f));
        *(float2*)o3 = make_float2(fmaxf(a01.y + b20, 0.f), fmaxf(a11.y + b21, 0.f));
    }
}

// ---------------- readout (blocks 0..7) + loss reduce (block 8) ----------------
__global__ void k_out(const float* __restrict__ X, const float* __restrict__ oW,
                      const float* __restrict__ ob, float* __restrict__ out) {
    if (blockIdx.x == 8) {
        __shared__ float red[256];
        int t = threadIdx.x;
        if (t < 256) {
            float a0 = 0.f, a1 = 0.f, a2 = 0.f, a3 = 0.f;
            for (int i = t * 4; i < BN; i += 1024) {
                a0 += g_term[i]; a1 += g_term[i + 1]; a2 += g_term[i + 2]; a3 += g_term[i + 3];
            }
            red[t] = (a0 + a1) + (a2 + a3);
        }
        __syncthreads();
        for (int s = 128; s > 0; s >>= 1) { if (t < s) red[t] += red[t + s]; __syncthreads(); }
        if (t == 0) out[80] = red[0];
        return;
    }
    __shared__ float S[320];
    int b = blockIdx.x, c = threadIdx.x;
    float a0 = 0.f, a1 = 0.f, a2 = 0.f, a3 = 0.f;
    if (c < 128) {
        const float* base = X + ((size_t)b * 512) * 128 + c;
        for (int n = 0; n < 512; n += 4) {
            a0 += base[n * 128]; a1 += base[(n + 1) * 128];
            a2 += base[(n + 2) * 128]; a3 += base[(n + 3) * 128];
        }
    } else {
        int l = (c - 128) / 64, cc = (c - 128) % 64;
        const float* base = g_h[l] + ((size_t)b * 512) * 64 + cc;
        for (int n = 0; n < 512; n += 4) {
            a0 += base[n * 64]; a1 += base[(n + 1) * 64];
            a2 += base[(n + 2) * 64]; a3 += base[(n + 3) * 64];
        }
    }
    S[c] = (a0 + a1) + (a2 + a3);
    __syncthreads();
    if (c < 10) {
        float o = ob[c];
        for (int k = 0; k < 320; k++) o = fmaf(S[k], oW[k * 10 + c], o);
        out[b * 10 + c] = o;
    }
}

// ---------------- launch ----------------
extern "C" void kernel_launch(void* const* d_in, const int* in_sizes, int n_in,
                              void* d_out, int out_size) {
    const float* X    = (const float*)d_in[0];
    const float* A    = (const float*)d_in[1];
    const int*   p    = (const int*)  d_in[2];
    const float* cW1  = (const float*)d_in[3];
    const float* cb1  = (const float*)d_in[4];
    const float* cW2  = (const float*)d_in[5];
    const float* cb2  = (const float*)d_in[6];
    const float* wmW1 = (const float*)d_in[7];
    const float* wmb1 = (const float*)d_in[8];
    const float* wmW2 = (const float*)d_in[9];
    const float* wmb2 = (const float*)d_in[10];
    const float* wmW3 = (const float*)d_in[11];
    const float* wmb3 = (const float*)d_in[12];
    const float* fnW1 = (const float*)d_in[13];
    const float* fnb1 = (const float*)d_in[14];
    const float* fnW2 = (const float*)d_in[15];
    const float* fnb2 = (const float*)d_in[16];
    const float* eps  = (const float*)d_in[17];
    const float* g0W1 = (const float*)d_in[18];
    const float* g0b1 = (const float*)d_in[19];
    const float* g0W2 = (const float*)d_in[20];
    const float* g0b2 = (const float*)d_in[21];
    const float* g1W1 = (const float*)d_in[22];
    const float* g1b1 = (const float*)d_in[23];
    const float* g1W2 = (const float*)d_in[24];
    const float* g1b2 = (const float*)d_in[25];
    const float* g2W1 = (const float*)d_in[26];
    const float* g2b1 = (const float*)d_in[27];
    const float* g2W2 = (const float*)d_in[28];
    const float* g2b2 = (const float*)d_in[29];
    const float* oW   = (const float*)d_in[30];
    const float* ob   = (const float*)d_in[31];
    float* out = (float*)d_out;

    float* h0 = nullptr;
    cudaGetSymbolAddress((void**)&h0, g_h);
    float* h1 = h0 + (size_t)BN * HH;
    float* h2 = h0 + (size_t)2 * BN * HH;

    const int SM_NODE  = (128 * 64 + 128 * 36 + 32 * 33) * 4;            // 55424
    const int SM_GIN0  = (128 * 64 + 64 * 64 + 128 * 36 + 64 * 36) * 4;  // 76800
    const int SM_GIN1  = (64 * 64 + 64 * 64 + 64 * 36 + 64 * 36) * 4;    // 51200
    cudaFuncSetAttribute(k_node,    cudaFuncAttributeMaxDynamicSharedMemorySize, SM_NODE);
    cudaFuncSetAttribute(k_gin<128>, cudaFuncAttributeMaxDynamicSharedMemorySize, SM_GIN0);
    cudaFuncSetAttribute(k_gin<64>,  cudaFuncAttributeMaxDynamicSharedMemorySize, SM_GIN1);

    k_adj <<<2049, 256>>>(A, wmW1, wmb1, wmW2, wmb2, wmW3, wmb3);
    k_node<<<128, 256, SM_NODE>>>(X, cW1, cb1, cW2, cb2, fnW1, fnb1, fnW2, fnb2);
    k_rank<<<dim3(8, 4), 128>>>();
    k_spmv1<<<512, 256>>>();
    k_spmv2<<<512, 256>>>();

    k_gin<128><<<128, 256, SM_GIN0>>>(X,  eps, p, 0, g0W1, g0b1, g0W2, g0b2, h0);
    k_gin<64> <<<128, 256, SM_GIN1>>>(h0, eps, p, 1, g1W1, g1b1, g1W2, g1b2, h1);
    k_gin<64> <<<128, 256, SM_GIN1>>>(h1, eps, p, 2, g2W1, g2b1, g2W2, g2b2, h2);

    k_out<<<9, 320>>>(X, oW, ob, out);
}